// round 1
// baseline (speedup 1.0000x reference)
#include <cuda_runtime.h>
#include <math.h>

#define B_   2
#define CIN  64
#define H_   80
#define W_   80
#define HW   6400

// ---------------- scratch (__device__ globals; no allocation allowed) ----------------
__device__ float g_xt[B_*HW*CIN];        // x transposed to [b][h][w][c]
__device__ float g_y3[B_*27*HW];         // conv out (offset raw + mask sigmoid), k=3
__device__ float g_y5[B_*75*HW];
__device__ float g_y7[B_*147*HW];
__device__ float g_w3[32*CIN*9];         // packed conv weights, oc padded to mult of 8
__device__ float g_w5[80*CIN*25];
__device__ float g_w7[152*CIN*49];
__device__ float g_b3[32];
__device__ float g_b5[80];
__device__ float g_b7[152];
__device__ float g_wd3[9*64*64];         // w_dcn repacked [tap][oc][c]
__device__ float g_wd5[25*64*64];
__device__ float g_wd7[49*64*64];

// ---------------- NCHW -> NHWC transpose ----------------
__global__ void transpose_kernel(const float* __restrict__ x, float* __restrict__ xt){
  __shared__ float s[64][33];
  int b   = blockIdx.x / 200;
  int hw0 = (blockIdx.x % 200) * 32;
  int tx = threadIdx.x & 31, ty = threadIdx.x >> 5;
  #pragma unroll
  for (int i = 0; i < 8; i++){
    int c = i*8 + ty;
    s[c][tx] = x[((size_t)(b*CIN + c))*HW + hw0 + tx];
  }
  __syncthreads();
  #pragma unroll
  for (int i = 0; i < 8; i++){
    int idx = i*256 + threadIdx.x;
    int hw = idx >> 6, c = idx & 63;
    xt[((size_t)b*HW + hw0 + hw)*CIN + c] = s[c][hw];
  }
}

// ---------------- weight packing ----------------
// wp: [OCP][CIN][KK]  (offset weights then mask weights, zero-padded ocs)
// bp: [OCP]
// wdp: [KK][64][64]   (w_dcn[o][c][j] -> [j][o][c])
__global__ void pack_kernel(const float* __restrict__ woff, const float* __restrict__ boff,
                            const float* __restrict__ wmask, const float* __restrict__ bmask,
                            const float* __restrict__ wdcn,
                            float* __restrict__ wp, float* __restrict__ bp, float* __restrict__ wdp,
                            int KK, int OCP){
  int CK = CIN*KK;
  int stride = gridDim.x * blockDim.x;
  int t0 = blockIdx.x*blockDim.x + threadIdx.x;
  for (int i = t0; i < OCP*CK; i += stride){
    int oc = i / CK, r = i % CK;
    float v = 0.f;
    if (oc < 2*KK)      v = woff[(size_t)oc*CK + r];
    else if (oc < 3*KK) v = wmask[(size_t)(oc-2*KK)*CK + r];
    wp[i] = v;
  }
  for (int i = t0; i < OCP; i += stride){
    float v = 0.f;
    if (i < 2*KK)      v = boff[i];
    else if (i < 3*KK) v = bmask[i-2*KK];
    bp[i] = v;
  }
  for (int i = t0; i < 64*CK; i += stride){
    int o = i / CK;
    int c = (i % CK) / KK;
    int j = i % KK;
    wdp[((size_t)j*64 + o)*64 + c] = wdcn[i];
  }
}

// ---------------- direct tiled conv (offset + mask in one pass) ----------------
// y[b][oc][h][w] for oc < Cout=3*KK; mask channels (oc >= 2*KK) get sigmoid.
template<int K>
__global__ void conv_kernel(const float* __restrict__ x, const float* __restrict__ wp,
                            const float* __restrict__ bp, float* __restrict__ y,
                            int Cout, int nOc){
  constexpr int KK = K*K, PAD = K/2, RH = 16 + K - 1, RW = 16 + K - 1;
  __shared__ __align__(16) float xs[8][RH][24];
  __shared__ __align__(16) float ws[8][KK][8];
  const int tid = threadIdx.x;
  const int tx = tid & 15, ty = tid >> 4;
  const int b   = blockIdx.z / nOc;
  const int occ = blockIdx.z % nOc;
  const int oc0 = occ * 8;
  const int tileX = blockIdx.x * 16, tileY = blockIdx.y * 16;

  float acc[8];
  #pragma unroll
  for (int o = 0; o < 8; o++) acc[o] = 0.f;

  for (int cc = 0; cc < CIN; cc += 8){
    // stage input tile (with halo, zero-padded)
    for (int i = tid; i < 8*RH*RW; i += 256){
      int c = i / (RH*RW);
      int rem = i % (RH*RW);
      int r = rem / RW, col = rem % RW;
      int gy = tileY - PAD + r, gx = tileX - PAD + col;
      float v = 0.f;
      if (gy >= 0 && gy < H_ && gx >= 0 && gx < W_)
        v = x[(((size_t)b*CIN + cc + c)*H_ + gy)*W_ + gx];
      xs[c][r][col] = v;
    }
    // stage weights: ws[c][j][o]
    for (int i = tid; i < 8*KK*8; i += 256){
      int j = i % KK;
      int o = (i / KK) & 7;
      int c = i / (KK*8);
      ws[c][j][o] = wp[(size_t)(oc0 + o)*(CIN*KK) + (size_t)(cc + c)*KK + j];
    }
    __syncthreads();
    #pragma unroll 2
    for (int c = 0; c < 8; c++){
      #pragma unroll
      for (int ky = 0; ky < K; ky++){
        #pragma unroll
        for (int kx = 0; kx < K; kx++){
          float xv = xs[c][ty + ky][tx + kx];
          const float4* w4 = (const float4*)&ws[c][ky*K + kx][0];
          float4 wa = w4[0], wb = w4[1];
          acc[0] += xv*wa.x; acc[1] += xv*wa.y; acc[2] += xv*wa.z; acc[3] += xv*wa.w;
          acc[4] += xv*wb.x; acc[5] += xv*wb.y; acc[6] += xv*wb.z; acc[7] += xv*wb.w;
        }
      }
    }
    __syncthreads();
  }

  int h = tileY + ty, w = tileX + tx;
  #pragma unroll
  for (int o = 0; o < 8; o++){
    int oc = oc0 + o;
    if (oc >= Cout) break;
    float v = acc[o] + bp[oc];
    if (oc >= 2*KK) v = 1.f/(1.f + __expf(-v));   // sigmoid for mask channels
    y[(((size_t)b*Cout + oc)*H_ + h)*W_ + w] = v;
  }
}

// ---------------- fused deformable sampling + DCN contraction ----------------
// Block: 16 pixels, 256 threads. Per tap: load w_dcn slice [64oc][64c] into smem,
// warp-per-pixel bilinear gather from NHWC x into smem (mask folded into weights),
// then thread = (1 oc, 4 px) FFMA contraction over 64 channels.
template<int K>
__global__ void dcn_kernel(const float* __restrict__ xt, const float* __restrict__ offm,
                           const float* __restrict__ wdp, float* __restrict__ out,
                           int outBase){
  constexpr int KK = K*K, PAD = K/2, C3 = 3*KK;
  __shared__ __align__(16) float ws[64][68];
  __shared__ __align__(16) float samp[16][68];
  const int tid  = threadIdx.x;
  const int b    = blockIdx.y;
  const int p0   = blockIdx.x * 16;
  const int oc   = tid >> 2;
  const int pxg  = tid & 3;
  const int wid  = tid >> 5;
  const int lane = tid & 31;
  const float* xb   = xt + (size_t)b*HW*CIN;
  const float* offb = offm + (size_t)b*C3*HW;
  float a0 = 0.f, a1 = 0.f, a2 = 0.f, a3 = 0.f;

  for (int j = 0; j < KK; j++){
    // weight slice for tap j (contiguous, coalesced float4)
    const float4* wsrc = (const float4*)(wdp + (size_t)j*4096);
    for (int i = tid; i < 1024; i += 256){
      int o = i >> 4, c4 = i & 15;
      ((float4*)&ws[o][0])[c4] = wsrc[i];
    }
    // bilinear gather: warp wid handles pixels wid and wid+8
    int iy = j / K, ix = j - iy*K;
    for (int p = wid; p < 16; p += 8){
      int pix = p0 + p;
      int h = pix / W_, w = pix - h*W_;
      float oy = __ldg(offb + (size_t)(2*j)*HW + pix);
      float ox = __ldg(offb + (size_t)(2*j + 1)*HW + pix);
      float m  = __ldg(offb + (size_t)(2*KK + j)*HW + pix);
      float py = (float)(h - PAD + iy) + oy;
      float px = (float)(w - PAD + ix) + ox;
      float y0f = floorf(py), x0f = floorf(px);
      float wy1 = py - y0f, wx1 = px - x0f;
      float wy0 = 1.f - wy1, wx0 = 1.f - wx1;
      int y0 = (int)y0f, x0 = (int)x0f;
      bool vy0 = (y0 >= 0)  && (y0 < H_);
      bool vy1 = (y0 >= -1) && (y0 < H_ - 1);
      bool vx0 = (x0 >= 0)  && (x0 < W_);
      bool vx1 = (x0 >= -1) && (x0 < W_ - 1);
      float w00 = (vy0 && vx0) ? wy0*wx0*m : 0.f;
      float w01 = (vy0 && vx1) ? wy0*wx1*m : 0.f;
      float w10 = (vy1 && vx0) ? wy1*wx0*m : 0.f;
      float w11 = (vy1 && vx1) ? wy1*wx1*m : 0.f;
      int y0c = min(max(y0, 0), H_-1), y1c = min(max(y0 + 1, 0), H_-1);
      int x0c = min(max(x0, 0), W_-1), x1c = min(max(x0 + 1, 0), W_-1);
      int c = lane * 2;
      float2 t00 = *(const float2*)(xb + (size_t)(y0c*W_ + x0c)*CIN + c);
      float2 t01 = *(const float2*)(xb + (size_t)(y0c*W_ + x1c)*CIN + c);
      float2 t10 = *(const float2*)(xb + (size_t)(y1c*W_ + x0c)*CIN + c);
      float2 t11 = *(const float2*)(xb + (size_t)(y1c*W_ + x1c)*CIN + c);
      float vx = w00*t00.x + w01*t01.x + w10*t10.x + w11*t11.x;
      float vy = w00*t00.y + w01*t01.y + w10*t10.y + w11*t11.y;
      *(float2*)&samp[p][c] = make_float2(vx, vy);
    }
    __syncthreads();
    // contraction: out[oc][p] += sum_c samp[p][c] * ws[oc][c]
    const float4* wrow = (const float4*)&ws[oc][0];
    const float4* s0 = (const float4*)&samp[pxg*4 + 0][0];
    const float4* s1 = (const float4*)&samp[pxg*4 + 1][0];
    const float4* s2 = (const float4*)&samp[pxg*4 + 2][0];
    const float4* s3 = (const float4*)&samp[pxg*4 + 3][0];
    #pragma unroll
    for (int c4 = 0; c4 < 16; c4++){
      float4 wv = wrow[c4];
      float4 v0 = s0[c4], v1 = s1[c4], v2 = s2[c4], v3 = s3[c4];
      a0 += wv.x*v0.x; a1 += wv.x*v1.x; a2 += wv.x*v2.x; a3 += wv.x*v3.x;
      a0 += wv.y*v0.y; a1 += wv.y*v1.y; a2 += wv.y*v2.y; a3 += wv.y*v3.y;
      a0 += wv.z*v0.z; a1 += wv.z*v1.z; a2 += wv.z*v2.z; a3 += wv.z*v3.z;
      a0 += wv.w*v0.w; a1 += wv.w*v1.w; a2 += wv.w*v2.w; a3 += wv.w*v3.w;
    }
    __syncthreads();
  }

  size_t ob = (((size_t)b*192 + outBase + oc)*HW) + p0 + pxg*4;
  out[ob + 0] = a0; out[ob + 1] = a1; out[ob + 2] = a2; out[ob + 3] = a3;
}

// ---------------- launch ----------------
extern "C" void kernel_launch(void* const* d_in, const int* in_sizes, int n_in,
                              void* d_out, int out_size){
  const float* x       = (const float*)d_in[0];
  const float* w_off3  = (const float*)d_in[1];
  const float* b_off3  = (const float*)d_in[2];
  const float* w_mask3 = (const float*)d_in[3];
  const float* b_mask3 = (const float*)d_in[4];
  const float* w_dcn3  = (const float*)d_in[5];
  const float* w_off5  = (const float*)d_in[6];
  const float* b_off5  = (const float*)d_in[7];
  const float* w_mask5 = (const float*)d_in[8];
  const float* b_mask5 = (const float*)d_in[9];
  const float* w_dcn5  = (const float*)d_in[10];
  const float* w_off7  = (const float*)d_in[11];
  const float* b_off7  = (const float*)d_in[12];
  const float* w_mask7 = (const float*)d_in[13];
  const float* b_mask7 = (const float*)d_in[14];
  const float* w_dcn7  = (const float*)d_in[15];
  float* out = (float*)d_out;

  float *xt, *y3, *y5, *y7, *w3, *w5, *w7, *b3, *b5, *b7, *wd3, *wd5, *wd7;
  cudaGetSymbolAddress((void**)&xt,  g_xt);
  cudaGetSymbolAddress((void**)&y3,  g_y3);
  cudaGetSymbolAddress((void**)&y5,  g_y5);
  cudaGetSymbolAddress((void**)&y7,  g_y7);
  cudaGetSymbolAddress((void**)&w3,  g_w3);
  cudaGetSymbolAddress((void**)&w5,  g_w5);
  cudaGetSymbolAddress((void**)&w7,  g_w7);
  cudaGetSymbolAddress((void**)&b3,  g_b3);
  cudaGetSymbolAddress((void**)&b5,  g_b5);
  cudaGetSymbolAddress((void**)&b7,  g_b7);
  cudaGetSymbolAddress((void**)&wd3, g_wd3);
  cudaGetSymbolAddress((void**)&wd5, g_wd5);
  cudaGetSymbolAddress((void**)&wd7, g_wd7);

  transpose_kernel<<<400, 256>>>(x, xt);
  pack_kernel<<<64, 256>>>(w_off3, b_off3, w_mask3, b_mask3, w_dcn3, w3, b3, wd3, 9, 32);
  pack_kernel<<<64, 256>>>(w_off5, b_off5, w_mask5, b_mask5, w_dcn5, w5, b5, wd5, 25, 80);
  pack_kernel<<<64, 256>>>(w_off7, b_off7, w_mask7, b_mask7, w_dcn7, w7, b7, wd7, 49, 152);

  conv_kernel<3><<<dim3(5, 5, B_*4),  256>>>(x, w3, b3, y3, 27, 4);
  conv_kernel<5><<<dim3(5, 5, B_*10), 256>>>(x, w5, b5, y5, 75, 10);
  conv_kernel<7><<<dim3(5, 5, B_*19), 256>>>(x, w7, b7, y7, 147, 19);

  dcn_kernel<3><<<dim3(400, B_), 256>>>(xt, y3, wd3, out, 0);
  dcn_kernel<5><<<dim3(400, B_), 256>>>(xt, y5, wd5, out, 64);
  dcn_kernel<7><<<dim3(400, B_), 256>>>(xt, y7, wd7, out, 128);
}

// round 2
// speedup vs baseline: 1.9810x; 1.9810x over previous
#include <cuda_runtime.h>
#include <math.h>

#define B_   2
#define CIN  64
#define H_   80
#define W_   80
#define HW   6400

// ---------------- scratch ----------------
__device__ float g_xt[B_*HW*CIN];        // x transposed to [b][h][w][c]
__device__ float g_y3[B_*27*HW];
__device__ float g_y5[B_*75*HW];
__device__ float g_y7[B_*147*HW];
__device__ float g_w3[32*CIN*9];
__device__ float g_w5[80*CIN*25];
__device__ float g_w7[152*CIN*49];
__device__ float g_b3[32];
__device__ float g_b5[80];
__device__ float g_b7[152];
__device__ float g_wd3[9*64*64];         // w_dcn repacked [tap][oc][c]
__device__ float g_wd5[25*64*64];
__device__ float g_wd7[49*64*64];

// ---------------- NCHW -> NHWC transpose ----------------
__global__ void transpose_kernel(const float* __restrict__ x, float* __restrict__ xt){
  __shared__ float s[64][33];
  int b   = blockIdx.x / 200;
  int hw0 = (blockIdx.x % 200) * 32;
  int tx = threadIdx.x & 31, ty = threadIdx.x >> 5;
  #pragma unroll
  for (int i = 0; i < 8; i++){
    int c = i*8 + ty;
    s[c][tx] = x[((size_t)(b*CIN + c))*HW + hw0 + tx];
  }
  __syncthreads();
  #pragma unroll
  for (int i = 0; i < 8; i++){
    int idx = i*256 + threadIdx.x;
    int hw = idx >> 6, c = idx & 63;
    xt[((size_t)b*HW + hw0 + hw)*CIN + c] = s[c][hw];
  }
}

// ---------------- weight packing ----------------
__global__ void pack_kernel(const float* __restrict__ woff, const float* __restrict__ boff,
                            const float* __restrict__ wmask, const float* __restrict__ bmask,
                            const float* __restrict__ wdcn,
                            float* __restrict__ wp, float* __restrict__ bp, float* __restrict__ wdp,
                            int KK, int OCP){
  int CK = CIN*KK;
  int stride = gridDim.x * blockDim.x;
  int t0 = blockIdx.x*blockDim.x + threadIdx.x;
  for (int i = t0; i < OCP*CK; i += stride){
    int oc = i / CK, r = i % CK;
    float v = 0.f;
    if (oc < 2*KK)      v = woff[(size_t)oc*CK + r];
    else if (oc < 3*KK) v = wmask[(size_t)(oc-2*KK)*CK + r];
    wp[i] = v;
  }
  for (int i = t0; i < OCP; i += stride){
    float v = 0.f;
    if (i < 2*KK)      v = boff[i];
    else if (i < 3*KK) v = bmask[i-2*KK];
    bp[i] = v;
  }
  for (int i = t0; i < 64*CK; i += stride){
    int o = i / CK;
    int c = (i % CK) / KK;
    int j = i % KK;
    wdp[((size_t)j*64 + o)*64 + c] = wdcn[i];
  }
}

// ---------------- direct tiled conv: 32x16 tile, thread = 2px x 8oc ----------------
template<int K>
__global__ void conv_kernel(const float* __restrict__ x, const float* __restrict__ wp,
                            const float* __restrict__ bp, float* __restrict__ y,
                            int Cout, int nOc){
  constexpr int KK = K*K, PAD = K/2;
  constexpr int TH = 16, TW = 32;
  constexpr int RH = TH + K - 1, RW = TW + K - 1;
  constexpr int RWP = RW + 1;                  // odd pitch -> conflict-free across rows
  __shared__ __align__(16) float xs[8][RH][RWP];
  __shared__ __align__(16) float ws[8][KK][8];
  const int tid = threadIdx.x;
  const int tx = tid & 15, ty = tid >> 4;      // 16 x 16 threads
  const int b   = blockIdx.z / nOc;
  const int occ = blockIdx.z % nOc;
  const int oc0 = occ * 8;
  const int tileX = blockIdx.x * TW, tileY = blockIdx.y * TH;

  float acc0[8], acc1[8];
  #pragma unroll
  for (int o = 0; o < 8; o++){ acc0[o] = 0.f; acc1[o] = 0.f; }

  for (int cc = 0; cc < CIN; cc += 8){
    for (int i = tid; i < 8*RH*RW; i += 256){
      int c = i / (RH*RW);
      int rem = i % (RH*RW);
      int r = rem / RW, col = rem % RW;
      int gy = tileY - PAD + r, gx = tileX - PAD + col;
      float v = 0.f;
      if (gy >= 0 && gy < H_ && gx >= 0 && gx < W_)
        v = x[(((size_t)b*CIN + cc + c)*H_ + gy)*W_ + gx];
      xs[c][r][col] = v;
    }
    for (int i = tid; i < 8*KK*8; i += 256){
      int j = i % KK;
      int o = (i / KK) & 7;
      int c = i / (KK*8);
      ws[c][j][o] = wp[(size_t)(oc0 + o)*(CIN*KK) + (size_t)(cc + c)*KK + j];
    }
    __syncthreads();
    for (int c = 0; c < 8; c++){
      const float* xrow0 = &xs[c][ty][2*tx];
      #pragma unroll
      for (int ky = 0; ky < K; ky++){
        #pragma unroll
        for (int kx = 0; kx < K; kx++){
          float xv0 = xrow0[ky*RWP + kx];
          float xv1 = xrow0[ky*RWP + kx + 1];
          const float4* w4 = (const float4*)&ws[c][ky*K + kx][0];
          float4 wa = w4[0], wb = w4[1];
          acc0[0] += xv0*wa.x; acc1[0] += xv1*wa.x;
          acc0[1] += xv0*wa.y; acc1[1] += xv1*wa.y;
          acc0[2] += xv0*wa.z; acc1[2] += xv1*wa.z;
          acc0[3] += xv0*wa.w; acc1[3] += xv1*wa.w;
          acc0[4] += xv0*wb.x; acc1[4] += xv1*wb.x;
          acc0[5] += xv0*wb.y; acc1[5] += xv1*wb.y;
          acc0[6] += xv0*wb.z; acc1[6] += xv1*wb.z;
          acc0[7] += xv0*wb.w; acc1[7] += xv1*wb.w;
        }
      }
    }
    __syncthreads();
  }

  int h = tileY + ty, w = tileX + 2*tx;
  if (w < W_){
    #pragma unroll
    for (int o = 0; o < 8; o++){
      int oc = oc0 + o;
      if (oc >= Cout) break;
      float bv = bp[oc];
      float v0 = acc0[o] + bv;
      float v1 = acc1[o] + bv;
      if (oc >= 2*KK){
        v0 = 1.f/(1.f + __expf(-v0));
        v1 = 1.f/(1.f + __expf(-v1));
      }
      *(float2*)&y[(((size_t)b*Cout + oc)*H_ + h)*W_ + w] = make_float2(v0, v1);
    }
  }
}

// ---------------- fused deformable sampling + DCN contraction ----------------
// Block: 32 pixels, 256 threads. thread = (4 oc strided by 16) x (2 px).
template<int K>
__global__ void dcn_kernel(const float* __restrict__ xt, const float* __restrict__ offm,
                           const float* __restrict__ wdp, float* __restrict__ out,
                           int outBase){
  constexpr int KK = K*K, PAD = K/2, C3 = 3*KK;
  __shared__ __align__(16) float wsT[16][260];   // [c4][oc*4], transposed weights
  __shared__ __align__(16) float samp[32][68];
  const int tid  = threadIdx.x;
  const int b    = blockIdx.y;
  const int p0   = blockIdx.x * 32;
  const int o0   = tid & 15;                      // oc = o0 + 16k
  const int pg   = tid >> 4;                      // px = pg*2 + {0,1}
  const int wid  = tid >> 5;
  const int lane = tid & 31;
  const float* xb   = xt + (size_t)b*HW*CIN;
  const float* offb = offm + (size_t)b*C3*HW;

  float a00=0.f,a01=0.f,a10=0.f,a11=0.f,a20=0.f,a21=0.f,a30=0.f,a31=0.f;

  for (int j = 0; j < KK; j++){
    // stage weights transposed: wsT[c4][oc] (float4 granularity)
    const float4* wsrc = (const float4*)(wdp + (size_t)j*4096);
    #pragma unroll
    for (int i = tid; i < 1024; i += 256){
      float4 v = __ldg(wsrc + i);
      *(float4*)&wsT[i & 15][(i >> 4)*4] = v;
    }
    // bilinear gather: warp wid handles pixels wid*4 .. wid*4+3
    int iy = j / K, ix = j - iy*K;
    #pragma unroll
    for (int r = 0; r < 4; r++){
      int p = wid*4 + r;
      int pix = p0 + p;
      int h = pix / W_, w = pix - h*W_;
      float oy = __ldg(offb + (size_t)(2*j)*HW + pix);
      float ox = __ldg(offb + (size_t)(2*j + 1)*HW + pix);
      float m  = __ldg(offb + (size_t)(2*KK + j)*HW + pix);
      float py = (float)(h - PAD + iy) + oy;
      float px = (float)(w - PAD + ix) + ox;
      float y0f = floorf(py), x0f = floorf(px);
      float wy1 = py - y0f, wx1 = px - x0f;
      float wy0 = 1.f - wy1, wx0 = 1.f - wx1;
      int y0 = (int)y0f, x0 = (int)x0f;
      bool vy0 = (y0 >= 0)  && (y0 < H_);
      bool vy1 = (y0 >= -1) && (y0 < H_ - 1);
      bool vx0 = (x0 >= 0)  && (x0 < W_);
      bool vx1 = (x0 >= -1) && (x0 < W_ - 1);
      float w00 = (vy0 && vx0) ? wy0*wx0*m : 0.f;
      float w01 = (vy0 && vx1) ? wy0*wx1*m : 0.f;
      float w10 = (vy1 && vx0) ? wy1*wx0*m : 0.f;
      float w11 = (vy1 && vx1) ? wy1*wx1*m : 0.f;
      int y0c = min(max(y0, 0), H_-1), y1c = min(max(y0 + 1, 0), H_-1);
      int x0c = min(max(x0, 0), W_-1), x1c = min(max(x0 + 1, 0), W_-1);
      int c = lane * 2;
      float2 t00 = *(const float2*)(xb + (size_t)(y0c*W_ + x0c)*CIN + c);
      float2 t01 = *(const float2*)(xb + (size_t)(y0c*W_ + x1c)*CIN + c);
      float2 t10 = *(const float2*)(xb + (size_t)(y1c*W_ + x0c)*CIN + c);
      float2 t11 = *(const float2*)(xb + (size_t)(y1c*W_ + x1c)*CIN + c);
      float vx = w00*t00.x + w01*t01.x + w10*t10.x + w11*t11.x;
      float vy = w00*t00.y + w01*t01.y + w10*t10.y + w11*t11.y;
      *(float2*)&samp[p][c] = make_float2(vx, vy);
    }
    __syncthreads();
    // contraction: acc[k][i] += sum_c samp[pg*2+i][c] * wsT[c][o0+16k]
    #pragma unroll
    for (int c4 = 0; c4 < 16; c4++){
      float4 w0 = *(const float4*)&wsT[c4][(o0      )*4];
      float4 w1 = *(const float4*)&wsT[c4][(o0 + 16 )*4];
      float4 w2 = *(const float4*)&wsT[c4][(o0 + 32 )*4];
      float4 w3 = *(const float4*)&wsT[c4][(o0 + 48 )*4];
      float4 s0 = *(const float4*)&samp[pg*2    ][c4*4];
      float4 s1 = *(const float4*)&samp[pg*2 + 1][c4*4];
      a00 += w0.x*s0.x + w0.y*s0.y + w0.z*s0.z + w0.w*s0.w;
      a01 += w0.x*s1.x + w0.y*s1.y + w0.z*s1.z + w0.w*s1.w;
      a10 += w1.x*s0.x + w1.y*s0.y + w1.z*s0.z + w1.w*s0.w;
      a11 += w1.x*s1.x + w1.y*s1.y + w1.z*s1.z + w1.w*s1.w;
      a20 += w2.x*s0.x + w2.y*s0.y + w2.z*s0.z + w2.w*s0.w;
      a21 += w2.x*s1.x + w2.y*s1.y + w2.z*s1.z + w2.w*s1.w;
      a30 += w3.x*s0.x + w3.y*s0.y + w3.z*s0.z + w3.w*s0.w;
      a31 += w3.x*s1.x + w3.y*s1.y + w3.z*s1.z + w3.w*s1.w;
    }
    __syncthreads();
  }

  int pxb = p0 + pg*2;
  size_t base = ((size_t)b*192 + outBase)*HW;
  *(float2*)&out[base + (size_t)(o0      )*HW + pxb] = make_float2(a00, a01);
  *(float2*)&out[base + (size_t)(o0 + 16 )*HW + pxb] = make_float2(a10, a11);
  *(float2*)&out[base + (size_t)(o0 + 32 )*HW + pxb] = make_float2(a20, a21);
  *(float2*)&out[base + (size_t)(o0 + 48 )*HW + pxb] = make_float2(a30, a31);
}

// ---------------- launch ----------------
extern "C" void kernel_launch(void* const* d_in, const int* in_sizes, int n_in,
                              void* d_out, int out_size){
  const float* x       = (const float*)d_in[0];
  const float* w_off3  = (const float*)d_in[1];
  const float* b_off3  = (const float*)d_in[2];
  const float* w_mask3 = (const float*)d_in[3];
  const float* b_mask3 = (const float*)d_in[4];
  const float* w_dcn3  = (const float*)d_in[5];
  const float* w_off5  = (const float*)d_in[6];
  const float* b_off5  = (const float*)d_in[7];
  const float* w_mask5 = (const float*)d_in[8];
  const float* b_mask5 = (const float*)d_in[9];
  const float* w_dcn5  = (const float*)d_in[10];
  const float* w_off7  = (const float*)d_in[11];
  const float* b_off7  = (const float*)d_in[12];
  const float* w_mask7 = (const float*)d_in[13];
  const float* b_mask7 = (const float*)d_in[14];
  const float* w_dcn7  = (const float*)d_in[15];
  float* out = (float*)d_out;

  float *xt, *y3, *y5, *y7, *w3, *w5, *w7, *b3, *b5, *b7, *wd3, *wd5, *wd7;
  cudaGetSymbolAddress((void**)&xt,  g_xt);
  cudaGetSymbolAddress((void**)&y3,  g_y3);
  cudaGetSymbolAddress((void**)&y5,  g_y5);
  cudaGetSymbolAddress((void**)&y7,  g_y7);
  cudaGetSymbolAddress((void**)&w3,  g_w3);
  cudaGetSymbolAddress((void**)&w5,  g_w5);
  cudaGetSymbolAddress((void**)&w7,  g_w7);
  cudaGetSymbolAddress((void**)&b3,  g_b3);
  cudaGetSymbolAddress((void**)&b5,  g_b5);
  cudaGetSymbolAddress((void**)&b7,  g_b7);
  cudaGetSymbolAddress((void**)&wd3, g_wd3);
  cudaGetSymbolAddress((void**)&wd5, g_wd5);
  cudaGetSymbolAddress((void**)&wd7, g_wd7);

  transpose_kernel<<<400, 256>>>(x, xt);
  pack_kernel<<<256, 256>>>(w_off3, b_off3, w_mask3, b_mask3, w_dcn3, w3, b3, wd3, 9, 32);
  pack_kernel<<<256, 256>>>(w_off5, b_off5, w_mask5, b_mask5, w_dcn5, w5, b5, wd5, 25, 80);
  pack_kernel<<<256, 256>>>(w_off7, b_off7, w_mask7, b_mask7, w_dcn7, w7, b7, wd7, 49, 152);

  conv_kernel<3><<<dim3(3, 5, B_*4),  256>>>(x, w3, b3, y3, 27, 4);
  conv_kernel<5><<<dim3(3, 5, B_*10), 256>>>(x, w5, b5, y5, 75, 10);
  conv_kernel<7><<<dim3(3, 5, B_*19), 256>>>(x, w7, b7, y7, 147, 19);

  dcn_kernel<3><<<dim3(200, B_), 256>>>(xt, y3, wd3, out, 0);
  dcn_kernel<5><<<dim3(200, B_), 256>>>(xt, y5, wd5, out, 64);
  dcn_kernel<7><<<dim3(200, B_), 256>>>(xt, y7, wd7, out, 128);
}

// round 4
// speedup vs baseline: 2.1614x; 1.0910x over previous
#include <cuda_runtime.h>
#include <math.h>
#include <stdint.h>

#define B_   2
#define CIN  64
#define H_   80
#define W_   80
#define HW   6400

typedef unsigned long long ull;

// ---------------- f32x2 packed-FMA helpers (Blackwell sm_100+ family) ----------------
__device__ __forceinline__ void fma2(ull& acc, ull a, ull b){
  asm("fma.rn.f32x2 %0, %1, %2, %0;" : "+l"(acc) : "l"(a), "l"(b));
}
__device__ __forceinline__ ull pack2(float lo, float hi){
  ull r;
  asm("mov.b64 %0, {%1, %2};" : "=l"(r) : "f"(lo), "f"(hi));
  return r;
}
__device__ __forceinline__ float2 unpack2(ull v){
  float lo, hi;
  asm("mov.b64 {%0, %1}, %2;" : "=f"(lo), "=f"(hi) : "l"(v));
  return make_float2(lo, hi);
}

// ---------------- scratch ----------------
__device__ float g_xt[B_*HW*CIN];        // x transposed to [b][h][w][c]
__device__ float g_y3[B_*27*HW];
__device__ float g_y5[B_*75*HW];
__device__ float g_y7[B_*147*HW];
__device__ float g_w3[32*CIN*9];
__device__ float g_w5[80*CIN*25];
__device__ float g_w7[152*CIN*49];
__device__ float g_b3[32];
__device__ float g_b5[80];
__device__ float g_b7[152];
__device__ float g_wd3[9*64*64];         // w_dcn repacked [tap][oc][c]
__device__ float g_wd5[25*64*64];
__device__ float g_wd7[49*64*64];

// ---------------- NCHW -> NHWC transpose ----------------
__global__ void transpose_kernel(const float* __restrict__ x, float* __restrict__ xt){
  __shared__ float s[64][33];
  int b   = blockIdx.x / 200;
  int hw0 = (blockIdx.x % 200) * 32;
  int tx = threadIdx.x & 31, ty = threadIdx.x >> 5;
  #pragma unroll
  for (int i = 0; i < 8; i++){
    int c = i*8 + ty;
    s[c][tx] = x[((size_t)(b*CIN + c))*HW + hw0 + tx];
  }
  __syncthreads();
  #pragma unroll
  for (int i = 0; i < 8; i++){
    int idx = i*256 + threadIdx.x;
    int hw = idx >> 6, c = idx & 63;
    xt[((size_t)b*HW + hw0 + hw)*CIN + c] = s[c][hw];
  }
}

// ---------------- weight packing ----------------
__global__ void pack_kernel(const float* __restrict__ woff, const float* __restrict__ boff,
                            const float* __restrict__ wmask, const float* __restrict__ bmask,
                            const float* __restrict__ wdcn,
                            float* __restrict__ wp, float* __restrict__ bp, float* __restrict__ wdp,
                            int KK, int OCP){
  int CK = CIN*KK;
  int stride = gridDim.x * blockDim.x;
  int t0 = blockIdx.x*blockDim.x + threadIdx.x;
  for (int i = t0; i < OCP*CK; i += stride){
    int oc = i / CK, r = i % CK;
    float v = 0.f;
    if (oc < 2*KK)      v = woff[(size_t)oc*CK + r];
    else if (oc < 3*KK) v = wmask[(size_t)(oc-2*KK)*CK + r];
    wp[i] = v;
  }
  for (int i = t0; i < OCP; i += stride){
    float v = 0.f;
    if (i < 2*KK)      v = boff[i];
    else if (i < 3*KK) v = bmask[i-2*KK];
    bp[i] = v;
  }
  for (int i = t0; i < 64*CK; i += stride){
    int o = i / CK;
    int c = (i % CK) / KK;
    int j = i % KK;
    wdp[((size_t)j*64 + o)*64 + c] = wdcn[i];
  }
}

// ---------------- direct tiled conv: 32x16 tile, thread = 2px x 8oc, FFMA2 ----------------
template<int K>
__global__ void conv_kernel(const float* __restrict__ x, const float* __restrict__ wp,
                            const float* __restrict__ bp, float* __restrict__ y,
                            int Cout, int nOc){
  constexpr int KK = K*K, PAD = K/2;
  constexpr int TH = 16, TW = 32;
  constexpr int RH = TH + K - 1, RW = TW + K - 1;
  constexpr int RWP = RW + 1;
  __shared__ __align__(16) float xs[8][RH][RWP];
  __shared__ __align__(16) float ws[8][KK][8];
  const int tid = threadIdx.x;
  const int tx = tid & 15, ty = tid >> 4;
  const int b   = blockIdx.z / nOc;
  const int occ = blockIdx.z % nOc;
  const int oc0 = occ * 8;
  const int tileX = blockIdx.x * TW, tileY = blockIdx.y * TH;

  // acc pairs over oc: accNp[i] = (oc0+2i, oc0+2i+1) for pixel N
  ull acc0p[4], acc1p[4];
  #pragma unroll
  for (int i = 0; i < 4; i++){ acc0p[i] = pack2(0.f, 0.f); acc1p[i] = pack2(0.f, 0.f); }

  for (int cc = 0; cc < CIN; cc += 8){
    for (int i = tid; i < 8*RH*RW; i += 256){
      int c = i / (RH*RW);
      int rem = i % (RH*RW);
      int r = rem / RW, col = rem % RW;
      int gy = tileY - PAD + r, gx = tileX - PAD + col;
      float v = 0.f;
      if (gy >= 0 && gy < H_ && gx >= 0 && gx < W_)
        v = x[(((size_t)b*CIN + cc + c)*H_ + gy)*W_ + gx];
      xs[c][r][col] = v;
    }
    for (int i = tid; i < 8*KK*8; i += 256){
      int j = i % KK;
      int o = (i / KK) & 7;
      int c = i / (KK*8);
      ws[c][j][o] = wp[(size_t)(oc0 + o)*(CIN*KK) + (size_t)(cc + c)*KK + j];
    }
    __syncthreads();
    for (int c = 0; c < 8; c++){
      const float* xrow0 = &xs[c][ty][2*tx];
      #pragma unroll
      for (int ky = 0; ky < K; ky++){
        #pragma unroll
        for (int kx = 0; kx < K; kx++){
          float xv0 = xrow0[ky*RWP + kx];
          float xv1 = xrow0[ky*RWP + kx + 1];
          ull x0p = pack2(xv0, xv0);
          ull x1p = pack2(xv1, xv1);
          const ulonglong2* w2 = (const ulonglong2*)&ws[c][ky*K + kx][0];
          ulonglong2 wA = w2[0], wB = w2[1];   // (w0,w1),(w2,w3) / (w4,w5),(w6,w7)
          fma2(acc0p[0], x0p, wA.x); fma2(acc0p[1], x0p, wA.y);
          fma2(acc0p[2], x0p, wB.x); fma2(acc0p[3], x0p, wB.y);
          fma2(acc1p[0], x1p, wA.x); fma2(acc1p[1], x1p, wA.y);
          fma2(acc1p[2], x1p, wB.x); fma2(acc1p[3], x1p, wB.y);
        }
      }
    }
    __syncthreads();
  }

  int h = tileY + ty, w = tileX + 2*tx;
  if (w < W_){
    #pragma unroll
    for (int i = 0; i < 4; i++){
      float2 v0 = unpack2(acc0p[i]);   // (ocA@px0, ocB@px0)
      float2 v1 = unpack2(acc1p[i]);   // (ocA@px1, ocB@px1)
      int ocA = oc0 + 2*i, ocB = ocA + 1;
      if (ocA < Cout){
        float bv = bp[ocA];
        float a0 = v0.x + bv, a1 = v1.x + bv;
        if (ocA >= 2*KK){ a0 = 1.f/(1.f + __expf(-a0)); a1 = 1.f/(1.f + __expf(-a1)); }
        *(float2*)&y[(((size_t)b*Cout + ocA)*H_ + h)*W_ + w] = make_float2(a0, a1);
      }
      if (ocB < Cout){
        float bv = bp[ocB];
        float a0 = v0.y + bv, a1 = v1.y + bv;
        if (ocB >= 2*KK){ a0 = 1.f/(1.f + __expf(-a0)); a1 = 1.f/(1.f + __expf(-a1)); }
        *(float2*)&y[(((size_t)b*Cout + ocB)*H_ + h)*W_ + w] = make_float2(a0, a1);
      }
    }
  }
}

// ---------------- fused deformable sampling + DCN contraction (FFMA2) ----------------
template<int K>
__global__ void dcn_kernel(const float* __restrict__ xt, const float* __restrict__ offm,
                           const float* __restrict__ wdp, float* __restrict__ out,
                           int outBase){
  constexpr int KK = K*K, PAD = K/2, C3 = 3*KK;
  __shared__ __align__(16) float wsT[16][260];
  __shared__ __align__(16) float samp[32][68];
  const int tid  = threadIdx.x;
  const int b    = blockIdx.y;
  const int p0   = blockIdx.x * 32;
  const int o0   = tid & 15;
  const int pg   = tid >> 4;
  const int wid  = tid >> 5;
  const int lane = tid & 31;
  const float* xb   = xt + (size_t)b*HW*CIN;
  const float* offb = offm + (size_t)b*C3*HW;

  // pair-accumulators: (even-c partial, odd-c partial) per (oc-group k, pixel i)
  ull p00, p01, p10, p11, p20, p21, p30, p31;
  p00=p01=p10=p11=p20=p21=p30=p31 = pack2(0.f, 0.f);

  for (int j = 0; j < KK; j++){
    const float4* wsrc = (const float4*)(wdp + (size_t)j*4096);
    #pragma unroll
    for (int i = tid; i < 1024; i += 256){
      float4 v = __ldg(wsrc + i);
      *(float4*)&wsT[i & 15][(i >> 4)*4] = v;
    }
    int iy = j / K, ix = j - iy*K;
    #pragma unroll
    for (int r = 0; r < 4; r++){
      int p = wid*4 + r;
      int pix = p0 + p;
      int h = pix / W_, w = pix - h*W_;
      float oy = __ldg(offb + (size_t)(2*j)*HW + pix);
      float ox = __ldg(offb + (size_t)(2*j + 1)*HW + pix);
      float m  = __ldg(offb + (size_t)(2*KK + j)*HW + pix);
      float py = (float)(h - PAD + iy) + oy;
      float px = (float)(w - PAD + ix) + ox;
      float y0f = floorf(py), x0f = floorf(px);
      float wy1 = py - y0f, wx1 = px - x0f;
      float wy0 = 1.f - wy1, wx0 = 1.f - wx1;
      int y0 = (int)y0f, x0 = (int)x0f;
      bool vy0 = (y0 >= 0)  && (y0 < H_);
      bool vy1 = (y0 >= -1) && (y0 < H_ - 1);
      bool vx0 = (x0 >= 0)  && (x0 < W_);
      bool vx1 = (x0 >= -1) && (x0 < W_ - 1);
      float w00 = (vy0 && vx0) ? wy0*wx0*m : 0.f;
      float w01 = (vy0 && vx1) ? wy0*wx1*m : 0.f;
      float w10 = (vy1 && vx0) ? wy1*wx0*m : 0.f;
      float w11 = (vy1 && vx1) ? wy1*wx1*m : 0.f;
      int y0c = min(max(y0, 0), H_-1), y1c = min(max(y0 + 1, 0), H_-1);
      int x0c = min(max(x0, 0), W_-1), x1c = min(max(x0 + 1, 0), W_-1);
      int c = lane * 2;
      float2 t00 = *(const float2*)(xb + (size_t)(y0c*W_ + x0c)*CIN + c);
      float2 t01 = *(const float2*)(xb + (size_t)(y0c*W_ + x1c)*CIN + c);
      float2 t10 = *(const float2*)(xb + (size_t)(y1c*W_ + x0c)*CIN + c);
      float2 t11 = *(const float2*)(xb + (size_t)(y1c*W_ + x1c)*CIN + c);
      float vx = w00*t00.x + w01*t01.x + w10*t10.x + w11*t11.x;
      float vy = w00*t00.y + w01*t01.y + w10*t10.y + w11*t11.y;
      *(float2*)&samp[p][c] = make_float2(vx, vy);
    }
    __syncthreads();
    #pragma unroll
    for (int c4 = 0; c4 < 16; c4++){
      ulonglong2 w0 = *(const ulonglong2*)&wsT[c4][(o0      )*4];
      ulonglong2 w1 = *(const ulonglong2*)&wsT[c4][(o0 + 16 )*4];
      ulonglong2 w2 = *(const ulonglong2*)&wsT[c4][(o0 + 32 )*4];
      ulonglong2 w3 = *(const ulonglong2*)&wsT[c4][(o0 + 48 )*4];
      ulonglong2 s0 = *(const ulonglong2*)&samp[pg*2    ][c4*4];
      ulonglong2 s1 = *(const ulonglong2*)&samp[pg*2 + 1][c4*4];
      fma2(p00, w0.x, s0.x); fma2(p00, w0.y, s0.y);
      fma2(p01, w0.x, s1.x); fma2(p01, w0.y, s1.y);
      fma2(p10, w1.x, s0.x); fma2(p10, w1.y, s0.y);
      fma2(p11, w1.x, s1.x); fma2(p11, w1.y, s1.y);
      fma2(p20, w2.x, s0.x); fma2(p20, w2.y, s0.y);
      fma2(p21, w2.x, s1.x); fma2(p21, w2.y, s1.y);
      fma2(p30, w3.x, s0.x); fma2(p30, w3.y, s0.y);
      fma2(p31, w3.x, s1.x); fma2(p31, w3.y, s1.y);
    }
    __syncthreads();
  }

  float2 u;
  float a00, a01, a10, a11, a20, a21, a30, a31;
  u = unpack2(p00); a00 = u.x + u.y;
  u = unpack2(p01); a01 = u.x + u.y;
  u = unpack2(p10); a10 = u.x + u.y;
  u = unpack2(p11); a11 = u.x + u.y;
  u = unpack2(p20); a20 = u.x + u.y;
  u = unpack2(p21); a21 = u.x + u.y;
  u = unpack2(p30); a30 = u.x + u.y;
  u = unpack2(p31); a31 = u.x + u.y;

  int pxb = p0 + pg*2;
  size_t base = ((size_t)b*192 + outBase)*HW;
  *(float2*)&out[base + (size_t)(o0      )*HW + pxb] = make_float2(a00, a01);
  *(float2*)&out[base + (size_t)(o0 + 16 )*HW + pxb] = make_float2(a10, a11);
  *(float2*)&out[base + (size_t)(o0 + 32 )*HW + pxb] = make_float2(a20, a21);
  *(float2*)&out[base + (size_t)(o0 + 48 )*HW + pxb] = make_float2(a30, a31);
}

// ---------------- launch ----------------
extern "C" void kernel_launch(void* const* d_in, const int* in_sizes, int n_in,
                              void* d_out, int out_size){
  const float* x       = (const float*)d_in[0];
  const float* w_off3  = (const float*)d_in[1];
  const float* b_off3  = (const float*)d_in[2];
  const float* w_mask3 = (const float*)d_in[3];
  const float* b_mask3 = (const float*)d_in[4];
  const float* w_dcn3  = (const float*)d_in[5];
  const float* w_off5  = (const float*)d_in[6];
  const float* b_off5  = (const float*)d_in[7];
  const float* w_mask5 = (const float*)d_in[8];
  const float* b_mask5 = (const float*)d_in[9];
  const float* w_dcn5  = (const float*)d_in[10];
  const float* w_off7  = (const float*)d_in[11];
  const float* b_off7  = (const float*)d_in[12];
  const float* w_mask7 = (const float*)d_in[13];
  const float* b_mask7 = (const float*)d_in[14];
  const float* w_dcn7  = (const float*)d_in[15];
  float* out = (float*)d_out;

  float *xt, *y3, *y5, *y7, *w3, *w5, *w7, *b3, *b5, *b7, *wd3, *wd5, *wd7;
  cudaGetSymbolAddress((void**)&xt,  g_xt);
  cudaGetSymbolAddress((void**)&y3,  g_y3);
  cudaGetSymbolAddress((void**)&y5,  g_y5);
  cudaGetSymbolAddress((void**)&y7,  g_y7);
  cudaGetSymbolAddress((void**)&w3,  g_w3);
  cudaGetSymbolAddress((void**)&w5,  g_w5);
  cudaGetSymbolAddress((void**)&w7,  g_w7);
  cudaGetSymbolAddress((void**)&b3,  g_b3);
  cudaGetSymbolAddress((void**)&b5,  g_b5);
  cudaGetSymbolAddress((void**)&b7,  g_b7);
  cudaGetSymbolAddress((void**)&wd3, g_wd3);
  cudaGetSymbolAddress((void**)&wd5, g_wd5);
  cudaGetSymbolAddress((void**)&wd7, g_wd7);

  transpose_kernel<<<400, 256>>>(x, xt);
  pack_kernel<<<256, 256>>>(w_off3, b_off3, w_mask3, b_mask3, w_dcn3, w3, b3, wd3, 9, 32);
  pack_kernel<<<256, 256>>>(w_off5, b_off5, w_mask5, b_mask5, w_dcn5, w5, b5, wd5, 25, 80);
  pack_kernel<<<256, 256>>>(w_off7, b_off7, w_mask7, b_mask7, w_dcn7, w7, b7, wd7, 49, 152);

  conv_kernel<3><<<dim3(3, 5, B_*4),  256>>>(x, w3, b3, y3, 27, 4);
  conv_kernel<5><<<dim3(3, 5, B_*10), 256>>>(x, w5, b5, y5, 75, 10);
  conv_kernel<7><<<dim3(3, 5, B_*19), 256>>>(x, w7, b7, y7, 147, 19);

  dcn_kernel<3><<<dim3(200, B_), 256>>>(xt, y3, wd3, out, 0);
  dcn_kernel<5><<<dim3(200, B_), 256>>>(xt, y5, wd5, out, 64);
  dcn_kernel<7><<<dim3(200, B_), 256>>>(xt, y7, wd7, out, 128);
}

// round 5
// speedup vs baseline: 2.8351x; 1.3117x over previous
#include <cuda_runtime.h>
#include <cuda_bf16.h>
#include <math.h>
#include <stdint.h>

#define B_   2
#define CIN  64
#define H_   80
#define W_   80
#define HW   6400

typedef unsigned long long ull;

// ---------------- f32x2 packed-FMA helpers ----------------
__device__ __forceinline__ void fma2(ull& acc, ull a, ull b){
  asm("fma.rn.f32x2 %0, %1, %2, %0;" : "+l"(acc) : "l"(a), "l"(b));
}
__device__ __forceinline__ ull pack2(float lo, float hi){
  ull r;
  asm("mov.b64 %0, {%1, %2};" : "=l"(r) : "f"(lo), "f"(hi));
  return r;
}
__device__ __forceinline__ float2 unpack2(ull v){
  float lo, hi;
  asm("mov.b64 {%0, %1}, %2;" : "=f"(lo), "=f"(hi) : "l"(v));
  return make_float2(lo, hi);
}

// ---------------- mma.sync m16n8k16 bf16 (sm_80+ baseline, fallback HMMA) ----------------
__device__ __forceinline__ void mma16816(float* c, uint32_t a0, uint32_t a1, uint32_t a2, uint32_t a3,
                                         uint32_t b0, uint32_t b1){
  asm volatile("mma.sync.aligned.m16n8k16.row.col.f32.bf16.bf16.f32 "
    "{%0,%1,%2,%3}, {%4,%5,%6,%7}, {%8,%9}, {%0,%1,%2,%3};"
    : "+f"(c[0]), "+f"(c[1]), "+f"(c[2]), "+f"(c[3])
    : "r"(a0), "r"(a1), "r"(a2), "r"(a3), "r"(b0), "r"(b1));
}

// ---------------- scratch ----------------
__device__ __align__(16) float g_xt[B_*HW*CIN];             // fp32 NHWC for dcn gather
__device__ __align__(16) __nv_bfloat16 g_xhi[B_*HW*CIN];    // bf16 hi NHWC
__device__ __align__(16) __nv_bfloat16 g_xlo[B_*HW*CIN];    // bf16 lo NHWC
__device__ float g_y3[B_*27*HW];
__device__ float g_y5[B_*75*HW];
__device__ float g_y7[B_*147*HW];
__device__ float g_b3[32];
__device__ float g_b5[80];
__device__ float g_b7[160];
__device__ float g_wd3[9*64*64];          // w_dcn repacked [tap][oc][c]
__device__ float g_wd5[25*64*64];
__device__ float g_wd7[49*64*64];
// conv weights bf16, [tap][split(hi,lo)][NP][64]
__device__ __align__(16) __nv_bfloat16 g_gw3[9*2*32*64];
__device__ __align__(16) __nv_bfloat16 g_gw5[25*2*80*64];
__device__ __align__(16) __nv_bfloat16 g_gw7[49*2*160*64];

// ---------------- NCHW -> NHWC transpose (+ bf16 hi/lo split) ----------------
__global__ void transpose_kernel(const float* __restrict__ x, float* __restrict__ xt,
                                 __nv_bfloat16* __restrict__ xhi, __nv_bfloat16* __restrict__ xlo){
  __shared__ float s[64][33];
  int b   = blockIdx.x / 200;
  int hw0 = (blockIdx.x % 200) * 32;
  int tx = threadIdx.x & 31, ty = threadIdx.x >> 5;
  #pragma unroll
  for (int i = 0; i < 8; i++){
    int c = i*8 + ty;
    s[c][tx] = x[((size_t)(b*CIN + c))*HW + hw0 + tx];
  }
  __syncthreads();
  #pragma unroll
  for (int i = 0; i < 8; i++){
    int idx = i*256 + threadIdx.x;
    int hw = idx >> 6, c = idx & 63;
    float v = s[c][hw];
    size_t o = ((size_t)b*HW + hw0 + hw)*CIN + c;
    xt[o] = v;
    __nv_bfloat16 hi = __float2bfloat16(v);
    xhi[o] = hi;
    xlo[o] = __float2bfloat16(v - __bfloat162float(hi));
  }
}

// ---------------- weight packing ----------------
__global__ void pack_kernel(const float* __restrict__ woff, const float* __restrict__ boff,
                            const float* __restrict__ wmask, const float* __restrict__ bmask,
                            const float* __restrict__ wdcn,
                            __nv_bfloat16* __restrict__ gw, float* __restrict__ bp,
                            float* __restrict__ wdp, int KK, int NP){
  int CK = CIN*KK;
  int stride = gridDim.x * blockDim.x;
  int t0 = blockIdx.x*blockDim.x + threadIdx.x;
  // gw[tap][split][n][64]
  for (int i = t0; i < KK*2*NP*64; i += stride){
    int tap = i / (2*NP*64);
    int s   = (i / (NP*64)) & 1;
    int n   = (i / 64) % NP;
    int c   = i & 63;
    float v = 0.f;
    if (n < 2*KK)      v = woff[((size_t)n*CIN + c)*KK + tap];
    else if (n < 3*KK) v = wmask[((size_t)(n-2*KK)*CIN + c)*KK + tap];
    __nv_bfloat16 hi = __float2bfloat16(v);
    gw[i] = (s == 0) ? hi : __float2bfloat16(v - __bfloat162float(hi));
  }
  for (int i = t0; i < NP; i += stride){
    float v = 0.f;
    if (i < 2*KK)      v = boff[i];
    else if (i < 3*KK) v = bmask[i-2*KK];
    bp[i] = v;
  }
  for (int i = t0; i < 64*CK; i += stride){
    int o = i / CK;
    int c = (i % CK) / KK;
    int j = i % KK;
    wdp[((size_t)j*64 + o)*64 + c] = wdcn[i];
  }
}

// ---------------- HMMA implicit-GEMM conv (offset+mask, bf16 3-split) ----------------
// CTA = 8x16 pixel tile, 8 warps (warp = one tile row of 16 px), NF = NP/8 n-frags.
// smem: xs[2][HR*WR][144B-pitch rows of 64 bf16], Bs[2][NP][144B pitch]
template<int K, int NP>
__global__ void conv_mma(const __nv_bfloat16* __restrict__ xhi, const __nv_bfloat16* __restrict__ xlo,
                         const __nv_bfloat16* __restrict__ gw, const float* __restrict__ bp,
                         float* __restrict__ y){
  constexpr int KK = K*K, PAD = K/2, Cout = 3*KK, NF = NP/8;
  constexpr int HR = 8 + K - 1, WR = 16 + K - 1;
  constexpr int PITCH = 144;                  // bytes per 64-bf16 row (conflict-free frags)
  constexpr int XS_SPLIT = HR*WR*PITCH;       // bytes per split
  constexpr int BS_OFF   = 2*XS_SPLIT;
  constexpr int BS_SPLIT = NP*PITCH;

  extern __shared__ __align__(16) char smem[];
  char* xs = smem;
  char* Bs = smem + BS_OFF;

  const int tid  = threadIdx.x;
  const int warp = tid >> 5;
  const int lane = tid & 31;
  const int blk = blockIdx.x;
  const int b = blk / 50;
  const int t = blk % 50;
  const int ty0 = (t / 5) * 8;
  const int tx0 = (t % 5) * 16;

  // ---- stage x halo tile (hi + lo) ----
  for (int i = tid; i < HR*WR*8; i += 256){
    int hp = i >> 3, c16 = i & 7;
    int gy = ty0 - PAD + hp / WR;
    int gx = tx0 - PAD + hp % WR;
    uint4 vh = make_uint4(0,0,0,0), vl = make_uint4(0,0,0,0);
    if (gy >= 0 && gy < H_ && gx >= 0 && gx < W_){
      size_t idx = ((size_t)(b*HW + gy*W_ + gx))*64 + c16*8;
      vh = *(const uint4*)(xhi + idx);
      vl = *(const uint4*)(xlo + idx);
    }
    *(uint4*)(xs + hp*PITCH + c16*16) = vh;
    *(uint4*)(xs + XS_SPLIT + hp*PITCH + c16*16) = vl;
  }

  float acc[NF][4];
  #pragma unroll
  for (int nf = 0; nf < NF; nf++){
    acc[nf][0] = acc[nf][1] = acc[nf][2] = acc[nf][3] = 0.f;
  }

  const int q  = lane & 3;     // k-quad
  const int r8 = lane >> 2;    // row-in-8

  for (int tap = 0; tap < KK; tap++){
    // ---- stage B for this tap (hi + lo) ----
    for (int i = tid; i < 2*NP*8; i += 256){
      int s = i / (NP*8);
      int n = (i >> 3) % NP;
      int c16 = i & 7;
      uint4 v = *(const uint4*)(gw + (((size_t)tap*2 + s)*NP + n)*64 + c16*8);
      *(uint4*)(Bs + s*BS_SPLIT + n*PITCH + c16*16) = v;
    }
    __syncthreads();

    int iy = tap / K, ix = tap % K;
    // A fragment base: pixel (warp+iy, pc+ix) in halo coords; frag row = pc = r8 (+8)
    const char* abase = xs + ((warp + iy)*WR + ix + r8)*PITCH + q*4;

    #pragma unroll
    for (int ks = 0; ks < 4; ks++){
      uint32_t ah0 = *(const uint32_t*)(abase + ks*32);
      uint32_t ah1 = *(const uint32_t*)(abase + 8*PITCH + ks*32);
      uint32_t ah2 = *(const uint32_t*)(abase + ks*32 + 16);
      uint32_t ah3 = *(const uint32_t*)(abase + 8*PITCH + ks*32 + 16);
      uint32_t al0 = *(const uint32_t*)(abase + XS_SPLIT + ks*32);
      uint32_t al1 = *(const uint32_t*)(abase + XS_SPLIT + 8*PITCH + ks*32);
      uint32_t al2 = *(const uint32_t*)(abase + XS_SPLIT + ks*32 + 16);
      uint32_t al3 = *(const uint32_t*)(abase + XS_SPLIT + 8*PITCH + ks*32 + 16);
      #pragma unroll
      for (int nf = 0; nf < NF; nf++){
        const char* bbase = Bs + (nf*8 + r8)*PITCH + q*4 + ks*32;
        uint32_t bh0 = *(const uint32_t*)(bbase);
        uint32_t bh1 = *(const uint32_t*)(bbase + 16);
        uint32_t bl0 = *(const uint32_t*)(bbase + BS_SPLIT);
        uint32_t bl1 = *(const uint32_t*)(bbase + BS_SPLIT + 16);
        mma16816(acc[nf], ah0, ah1, ah2, ah3, bh0, bh1);
        mma16816(acc[nf], ah0, ah1, ah2, ah3, bl0, bl1);
        mma16816(acc[nf], al0, al1, al2, al3, bh0, bh1);
      }
    }
    __syncthreads();
  }

  // ---- epilogue: C frag -> y (NCHW), bias + sigmoid on mask channels ----
  const int h = ty0 + warp;
  const int col0 = (lane & 3)*2;
  #pragma unroll
  for (int nf = 0; nf < NF; nf++){
    #pragma unroll
    for (int e = 0; e < 4; e++){
      int oc = nf*8 + col0 + (e & 1);
      int pc = r8 + (e >> 1)*8;
      if (oc < Cout){
        float v = acc[nf][e] + __ldg(bp + oc);
        if (oc >= 2*KK) v = 1.f/(1.f + __expf(-v));
        y[((size_t)(b*Cout + oc))*HW + h*W_ + tx0 + pc] = v;
      }
    }
  }
}

// ---------------- fused deformable sampling + DCN contraction (FFMA2) ----------------
template<int K>
__global__ void dcn_kernel(const float* __restrict__ xt, const float* __restrict__ offm,
                           const float* __restrict__ wdp, float* __restrict__ out,
                           int outBase){
  constexpr int KK = K*K, PAD = K/2, C3 = 3*KK;
  __shared__ __align__(16) float wsT[16][260];
  __shared__ __align__(16) float samp[32][68];
  const int tid  = threadIdx.x;
  const int b    = blockIdx.y;
  const int p0   = blockIdx.x * 32;
  const int o0   = tid & 15;
  const int pg   = tid >> 4;
  const int wid  = tid >> 5;
  const int lane = tid & 31;
  const float* xb   = xt + (size_t)b*HW*CIN;
  const float* offb = offm + (size_t)b*C3*HW;

  ull p00, p01, p10, p11, p20, p21, p30, p31;
  p00=p01=p10=p11=p20=p21=p30=p31 = pack2(0.f, 0.f);

  for (int j = 0; j < KK; j++){
    const float4* wsrc = (const float4*)(wdp + (size_t)j*4096);
    #pragma unroll
    for (int i = tid; i < 1024; i += 256){
      float4 v = __ldg(wsrc + i);
      *(float4*)&wsT[i & 15][(i >> 4)*4] = v;
    }
    int iy = j / K, ix = j - iy*K;
    #pragma unroll
    for (int r = 0; r < 4; r++){
      int p = wid*4 + r;
      int pix = p0 + p;
      int h = pix / W_, w = pix - h*W_;
      float oy = __ldg(offb + (size_t)(2*j)*HW + pix);
      float ox = __ldg(offb + (size_t)(2*j + 1)*HW + pix);
      float m  = __ldg(offb + (size_t)(2*KK + j)*HW + pix);
      float py = (float)(h - PAD + iy) + oy;
      float px = (float)(w - PAD + ix) + ox;
      float y0f = floorf(py), x0f = floorf(px);
      float wy1 = py - y0f, wx1 = px - x0f;
      float wy0 = 1.f - wy1, wx0 = 1.f - wx1;
      int y0 = (int)y0f, x0 = (int)x0f;
      bool vy0 = (y0 >= 0)  && (y0 < H_);
      bool vy1 = (y0 >= -1) && (y0 < H_ - 1);
      bool vx0 = (x0 >= 0)  && (x0 < W_);
      bool vx1 = (x0 >= -1) && (x0 < W_ - 1);
      float w00 = (vy0 && vx0) ? wy0*wx0*m : 0.f;
      float w01 = (vy0 && vx1) ? wy0*wx1*m : 0.f;
      float w10 = (vy1 && vx0) ? wy1*wx0*m : 0.f;
      float w11 = (vy1 && vx1) ? wy1*wx1*m : 0.f;
      int y0c = min(max(y0, 0), H_-1), y1c = min(max(y0 + 1, 0), H_-1);
      int x0c = min(max(x0, 0), W_-1), x1c = min(max(x0 + 1, 0), W_-1);
      int c = lane * 2;
      float2 t00 = *(const float2*)(xb + (size_t)(y0c*W_ + x0c)*CIN + c);
      float2 t01 = *(const float2*)(xb + (size_t)(y0c*W_ + x1c)*CIN + c);
      float2 t10 = *(const float2*)(xb + (size_t)(y1c*W_ + x0c)*CIN + c);
      float2 t11 = *(const float2*)(xb + (size_t)(y1c*W_ + x1c)*CIN + c);
      float vx = w00*t00.x + w01*t01.x + w10*t10.x + w11*t11.x;
      float vy = w00*t00.y + w01*t01.y + w10*t10.y + w11*t11.y;
      *(float2*)&samp[p][c] = make_float2(vx, vy);
    }
    __syncthreads();
    #pragma unroll
    for (int c4 = 0; c4 < 16; c4++){
      ulonglong2 w0 = *(const ulonglong2*)&wsT[c4][(o0      )*4];
      ulonglong2 w1 = *(const ulonglong2*)&wsT[c4][(o0 + 16 )*4];
      ulonglong2 w2 = *(const ulonglong2*)&wsT[c4][(o0 + 32 )*4];
      ulonglong2 w3 = *(const ulonglong2*)&wsT[c4][(o0 + 48 )*4];
      ulonglong2 s0 = *(const ulonglong2*)&samp[pg*2    ][c4*4];
      ulonglong2 s1 = *(const ulonglong2*)&samp[pg*2 + 1][c4*4];
      fma2(p00, w0.x, s0.x); fma2(p00, w0.y, s0.y);
      fma2(p01, w0.x, s1.x); fma2(p01, w0.y, s1.y);
      fma2(p10, w1.x, s0.x); fma2(p10, w1.y, s0.y);
      fma2(p11, w1.x, s1.x); fma2(p11, w1.y, s1.y);
      fma2(p20, w2.x, s0.x); fma2(p20, w2.y, s0.y);
      fma2(p21, w2.x, s1.x); fma2(p21, w2.y, s1.y);
      fma2(p30, w3.x, s0.x); fma2(p30, w3.y, s0.y);
      fma2(p31, w3.x, s1.x); fma2(p31, w3.y, s1.y);
    }
    __syncthreads();
  }

  float2 u;
  float a00, a01, a10, a11, a20, a21, a30, a31;
  u = unpack2(p00); a00 = u.x + u.y;
  u = unpack2(p01); a01 = u.x + u.y;
  u = unpack2(p10); a10 = u.x + u.y;
  u = unpack2(p11); a11 = u.x + u.y;
  u = unpack2(p20); a20 = u.x + u.y;
  u = unpack2(p21); a21 = u.x + u.y;
  u = unpack2(p30); a30 = u.x + u.y;
  u = unpack2(p31); a31 = u.x + u.y;

  int pxb = p0 + pg*2;
  size_t base = ((size_t)b*192 + outBase)*HW;
  *(float2*)&out[base + (size_t)(o0      )*HW + pxb] = make_float2(a00, a01);
  *(float2*)&out[base + (size_t)(o0 + 16 )*HW + pxb] = make_float2(a10, a11);
  *(float2*)&out[base + (size_t)(o0 + 32 )*HW + pxb] = make_float2(a20, a21);
  *(float2*)&out[base + (size_t)(o0 + 48 )*HW + pxb] = make_float2(a30, a31);
}

// ---------------- launch ----------------
extern "C" void kernel_launch(void* const* d_in, const int* in_sizes, int n_in,
                              void* d_out, int out_size){
  const float* x       = (const float*)d_in[0];
  const float* w_off3  = (const float*)d_in[1];
  const float* b_off3  = (const float*)d_in[2];
  const float* w_mask3 = (const float*)d_in[3];
  const float* b_mask3 = (const float*)d_in[4];
  const float* w_dcn3  = (const float*)d_in[5];
  const float* w_off5  = (const float*)d_in[6];
  const float* b_off5  = (const float*)d_in[7];
  const float* w_mask5 = (const float*)d_in[8];
  const float* b_mask5 = (const float*)d_in[9];
  const float* w_dcn5  = (const float*)d_in[10];
  const float* w_off7  = (const float*)d_in[11];
  const float* b_off7  = (const float*)d_in[12];
  const float* w_mask7 = (const float*)d_in[13];
  const float* b_mask7 = (const float*)d_in[14];
  const float* w_dcn7  = (const float*)d_in[15];
  float* out = (float*)d_out;

  float *xt, *y3, *y5, *y7, *b3, *b5, *b7, *wd3, *wd5, *wd7;
  __nv_bfloat16 *xhi, *xlo, *gw3, *gw5, *gw7;
  cudaGetSymbolAddress((void**)&xt,  g_xt);
  cudaGetSymbolAddress((void**)&xhi, g_xhi);
  cudaGetSymbolAddress((void**)&xlo, g_xlo);
  cudaGetSymbolAddress((void**)&y3,  g_y3);
  cudaGetSymbolAddress((void**)&y5,  g_y5);
  cudaGetSymbolAddress((void**)&y7,  g_y7);
  cudaGetSymbolAddress((void**)&b3,  g_b3);
  cudaGetSymbolAddress((void**)&b5,  g_b5);
  cudaGetSymbolAddress((void**)&b7,  g_b7);
  cudaGetSymbolAddress((void**)&wd3, g_wd3);
  cudaGetSymbolAddress((void**)&wd5, g_wd5);
  cudaGetSymbolAddress((void**)&wd7, g_wd7);
  cudaGetSymbolAddress((void**)&gw3, g_gw3);
  cudaGetSymbolAddress((void**)&gw5, g_gw5);
  cudaGetSymbolAddress((void**)&gw7, g_gw7);

  // smem sizes: 2*HR*WR*144 + 2*NP*144
  const int smem3 = 2*10*18*144 + 2*32*144;    //  61056
  const int smem5 = 2*12*20*144 + 2*80*144;    //  92160
  const int smem7 = 2*14*22*144 + 2*160*144;   // 134784
  cudaFuncSetAttribute(conv_mma<3,32>,  cudaFuncAttributeMaxDynamicSharedMemorySize, smem3);
  cudaFuncSetAttribute(conv_mma<5,80>,  cudaFuncAttributeMaxDynamicSharedMemorySize, smem5);
  cudaFuncSetAttribute(conv_mma<7,160>, cudaFuncAttributeMaxDynamicSharedMemorySize, smem7);

  transpose_kernel<<<400, 256>>>(x, xt, xhi, xlo);
  pack_kernel<<<256, 256>>>(w_off3, b_off3, w_mask3, b_mask3, w_dcn3, gw3, b3, wd3, 9, 32);
  pack_kernel<<<256, 256>>>(w_off5, b_off5, w_mask5, b_mask5, w_dcn5, gw5, b5, wd5, 25, 80);
  pack_kernel<<<256, 256>>>(w_off7, b_off7, w_mask7, b_mask7, w_dcn7, gw7, b7, wd7, 49, 160);

  conv_mma<3,32> <<<100, 256, smem3>>>(xhi, xlo, gw3, b3, y3);
  conv_mma<5,80> <<<100, 256, smem5>>>(xhi, xlo, gw5, b5, y5);
  conv_mma<7,160><<<100, 256, smem7>>>(xhi, xlo, gw7, b7, y7);

  dcn_kernel<3><<<dim3(200, B_), 256>>>(xt, y3, wd3, out, 0);
  dcn_kernel<5><<<dim3(200, B_), 256>>>(xt, y5, wd5, out, 64);
  dcn_kernel<7><<<dim3(200, B_), 256>>>(xt, y7, wd7, out, 128);
}